// round 11
// baseline (speedup 1.0000x reference)
#include <cuda_runtime.h>
#include <cuda_fp16.h>
#include <math.h>
#include <stdint.h>

// Problem dims
#define BB 128
#define SS 64
#define UU 512
#define VV 32000
#define XCC 1024   // 2U
#define G3 1536    // 3U

// Output layout: [logits (128*32000)] [state (128*512)] [alpha (128*64)]
#define STATE_OFF (BB*VV)
#define ALPHA_OFF (BB*VV + BB*UU)

// Scratch (device globals: allocation-free). All explicitly 16B-aligned:
// vectorized (uint4/uint2) access below requires it; __half's natural
// alignment is only 2.
__device__ __align__(16) float  g_E[BB*SS*UU];       // tanh(attn@W0+b0+b1)
__device__ __align__(16) float  g_xc[BB*XCC];        // [emb gather | context]
__device__ __align__(16) float  g_U[BB*G3];          // xc@gru_k + gru_b[0]
__device__ __align__(16) __half g_yh[BB*UU];         // relu(state@dW+db), fp16
__device__ __align__(16) __half g_attn_h[BB*SS*UU];  // attn in fp16
__device__ __align__(16) __half g_W0t[UU*UU];        // W0^T fp16 [N][K]
__device__ __align__(16) __half g_oWt[(size_t)VV*UU];// oW^T fp16 [N][K]

__device__ __forceinline__ uint32_t f2tf32(float x) {
    uint32_t r; asm("cvt.rna.tf32.f32 %0, %1;" : "=r"(r) : "f"(x)); return r;
}

__device__ __forceinline__ uint32_t packh(float a, float b) {
    __half2 v;
    v.x = __float2half_rn(a);
    v.y = __float2half_rn(b);
    return *(uint32_t*)&v;
}

__device__ __forceinline__ void mma8(float* c, const uint32_t* a, const uint32_t* b) {
    asm volatile(
        "mma.sync.aligned.m16n8k8.row.col.f32.tf32.tf32.f32 "
        "{%0,%1,%2,%3},{%4,%5,%6,%7},{%8,%9},{%0,%1,%2,%3};"
        : "+f"(c[0]), "+f"(c[1]), "+f"(c[2]), "+f"(c[3])
        : "r"(a[0]), "r"(a[1]), "r"(a[2]), "r"(a[3]),
          "r"(b[0]), "r"(b[1]));
}

__device__ __forceinline__ void mma16h(float* c, const uint32_t* a, const uint32_t* b) {
    asm volatile(
        "mma.sync.aligned.m16n8k16.row.col.f32.f16.f16.f32 "
        "{%0,%1,%2,%3},{%4,%5,%6,%7},{%8,%9},{%0,%1,%2,%3};"
        : "+f"(c[0]), "+f"(c[1]), "+f"(c[2]), "+f"(c[3])
        : "r"(a[0]), "r"(a[1]), "r"(a[2]), "r"(a[3]),
          "r"(b[0]), "r"(b[1]));
}

// ---------------------------------------------------------------------------
// Pre-pass: f32 -> fp16 elementwise (same layout). n % 1024 == 0.
// ---------------------------------------------------------------------------
__global__ __launch_bounds__(256) void cvt_h(
    const float* __restrict__ src, __half* __restrict__ dst)
{
    const int i = (blockIdx.x * 256 + threadIdx.x) * 4;
    float4 v = *(const float4*)(src + i);
    *(uint2*)(dst + i) = make_uint2(packh(v.x, v.y), packh(v.z, v.w));
}

// ---------------------------------------------------------------------------
// Pre-pass: transpose + cvt: src f32 [K][N] -> dst fp16 [N][K]. 32x32 tiles.
// blockDim (32, 8). grid (N/32, K/32).
// ---------------------------------------------------------------------------
__global__ __launch_bounds__(256) void transpose_h(
    const float* __restrict__ src, __half* __restrict__ dst, int K, int N)
{
    __shared__ float t[32][33];
    const int n0 = blockIdx.x * 32;
    const int k0 = blockIdx.y * 32;
    const int tx = threadIdx.x;
#pragma unroll
    for (int j = threadIdx.y; j < 32; j += 8)
        t[j][tx] = src[(size_t)(k0 + j) * N + n0 + tx];
    __syncthreads();
#pragma unroll
    for (int j = threadIdx.y; j < 32; j += 8)
        dst[(size_t)(n0 + j) * K + k0 + tx] = __float2half_rn(t[tx][j]);
}

// ---------------------------------------------------------------------------
// FP16 mma.sync GEMM. Block 128x128, BK=32, 256 threads (8 warps 2x4),
// warp tile 64x32. Inputs pre-converted fp16:
//   A [M][K] row-major, Bt [N][K] row-major (B transposed).
// Static smem, single buffer: rows of 80 B (64 B data + pad) for both A and
// B tiles -> fill is 4 LDG.128 + 4 STS.128 per thread; fragment LDS
// conflict-free. Loop: fill -> sync -> compute -> sync.
// C = epi(...) f32. EPI: 0 bias, 1 bias1+bias2 tanh. K%32==0.
// ---------------------------------------------------------------------------
template<int EPI>
__global__ __launch_bounds__(256) void mma128h3(
    const __half* __restrict__ A, const __half* __restrict__ Bt,
    float* __restrict__ C,
    const float* __restrict__ bias1, const float* __restrict__ bias2,
    int M, int N, int K)
{
    __shared__ __align__(16) char smA[128 * 80];
    __shared__ __align__(16) char smB[128 * 80];

    const int tid  = threadIdx.x;
    const int warp = tid >> 5;
    const int lane = tid & 31;
    const int bm   = blockIdx.y * 128;
    const int bn   = blockIdx.x * 128;
    const int wm   = (warp >> 2) * 64;
    const int wn   = (warp & 3) * 32;
    const int lr   = lane >> 2;
    const int lc   = lane & 3;

    // Fill: thread t handles row (t>>1), 32-byte segment (t&1) of both tiles.
    const int f_row = tid >> 1;
    const int f_sh  = (tid & 1) * 16;   // half offset within row (0 or 16)
    const __half* pa = A  + (size_t)(bm + f_row) * K + f_sh;
    const __half* pb = Bt + (size_t)(bn + f_row) * K + f_sh;
    char* dA = smA + f_row * 80 + f_sh * 2;
    char* dB = smB + f_row * 80 + f_sh * 2;

    float acc[4][4][4];
#pragma unroll
    for (int mi = 0; mi < 4; mi++)
#pragma unroll
        for (int ni = 0; ni < 4; ni++)
#pragma unroll
            for (int q = 0; q < 4; q++) acc[mi][ni][q] = 0.0f;

    for (int k0 = 0; k0 < K; k0 += 32) {
        // ---- fill: 4 x LDG.128 + 4 x STS.128 ----
        uint4 a0 = *(const uint4*)(pa + k0);
        uint4 a1 = *(const uint4*)(pa + k0 + 8);
        uint4 b0 = *(const uint4*)(pb + k0);
        uint4 b1 = *(const uint4*)(pb + k0 + 8);
        *(uint4*)(dA)      = a0;
        *(uint4*)(dA + 16) = a1;
        *(uint4*)(dB)      = b0;
        *(uint4*)(dB + 16) = b1;
        __syncthreads();

        // ---- compute: 2 k16 slices ----
#pragma unroll
        for (int ks = 0; ks < 2; ks++) {
            const int kq = ks * 8;
            uint32_t af[4][4];
#pragma unroll
            for (int mi = 0; mi < 4; mi++) {
                const int r = wm + mi * 16 + lr;
                af[mi][0] = *(const uint32_t*)(smA + r * 80 + (kq + lc) * 4);
                af[mi][1] = *(const uint32_t*)(smA + (r + 8) * 80 + (kq + lc) * 4);
                af[mi][2] = *(const uint32_t*)(smA + r * 80 + (kq + 4 + lc) * 4);
                af[mi][3] = *(const uint32_t*)(smA + (r + 8) * 80 + (kq + 4 + lc) * 4);
            }
            uint32_t bf[4][2];
#pragma unroll
            for (int ni = 0; ni < 4; ni++) {
                const int cc = wn + ni * 8 + lr;
                bf[ni][0] = *(const uint32_t*)(smB + cc * 80 + (kq + lc) * 4);
                bf[ni][1] = *(const uint32_t*)(smB + cc * 80 + (kq + 4 + lc) * 4);
            }
#pragma unroll
            for (int mi = 0; mi < 4; mi++)
#pragma unroll
                for (int ni = 0; ni < 4; ni++)
                    mma16h(acc[mi][ni], af[mi], bf[ni]);
        }
        __syncthreads();
    }

    // Epilogue
#pragma unroll
    for (int mi = 0; mi < 4; mi++) {
#pragma unroll
        for (int ni = 0; ni < 4; ni++) {
            const int r0 = bm + wm + mi * 16 + lr;
            const int c0 = bn + wn + ni * 8 + lc * 2;
            float b1v0 = bias1 ? bias1[c0]     : 0.0f;
            float b1v1 = bias1 ? bias1[c0 + 1] : 0.0f;
#pragma unroll
            for (int h = 0; h < 2; h++) {
                float x0 = acc[mi][ni][h * 2 + 0] + b1v0;
                float x1 = acc[mi][ni][h * 2 + 1] + b1v1;
                if (EPI == 1) {
                    x0 = tanhf(x0 + bias2[c0]);
                    x1 = tanhf(x1 + bias2[c0 + 1]);
                }
                *(float2*)(C + (size_t)(r0 + h * 8) * N + c0) = make_float2(x0, x1);
            }
        }
    }
}

// ---------------------------------------------------------------------------
// TF32 MMA GEMM, 64x64 block tile, BK=32, 256 threads, warp tile 32x16.
// HOUT=1: write fp16 to Ch instead of f32 to C.
// ---------------------------------------------------------------------------
template<int EPI, int HOUT>
__global__ __launch_bounds__(256) void mma64(
    const float* __restrict__ A, const float* __restrict__ Bm,
    float* __restrict__ C, __half* __restrict__ Ch,
    const float* __restrict__ bias1,
    int M, int N, int K)
{
    __shared__ uint32_t As[64][36];
    __shared__ uint32_t Bs[32][72];

    const int tid  = threadIdx.x;
    const int warp = tid >> 5;
    const int lane = tid & 31;
    const int wm   = (warp >> 2) * 32;
    const int wn   = (warp & 3) * 16;
    const int bm   = blockIdx.y * 64;
    const int bn   = blockIdx.x * 64;
    const int lr   = lane >> 2;
    const int lc   = lane & 3;

    float acc[2][2][4];
#pragma unroll
    for (int mi = 0; mi < 2; mi++)
#pragma unroll
        for (int ni = 0; ni < 2; ni++)
#pragma unroll
            for (int q = 0; q < 4; q++) acc[mi][ni][q] = 0.0f;

    for (int k0 = 0; k0 < K; k0 += 32) {
#pragma unroll
        for (int it = 0; it < 2; it++) {
            const int idx = it * 256 + tid;
            const int r  = idx >> 3;
            const int kq = (idx & 7) * 4;
            float4 v = *(const float4*)(A + (size_t)(bm + r) * K + k0 + kq);
            As[r][kq + 0] = f2tf32(v.x);
            As[r][kq + 1] = f2tf32(v.y);
            As[r][kq + 2] = f2tf32(v.z);
            As[r][kq + 3] = f2tf32(v.w);
        }
#pragma unroll
        for (int it = 0; it < 2; it++) {
            const int idx = it * 256 + tid;
            const int r  = idx >> 4;
            const int cq = (idx & 15) * 4;
            float4 v = *(const float4*)(Bm + (size_t)(k0 + r) * N + bn + cq);
            Bs[r][cq + 0] = f2tf32(v.x);
            Bs[r][cq + 1] = f2tf32(v.y);
            Bs[r][cq + 2] = f2tf32(v.z);
            Bs[r][cq + 3] = f2tf32(v.w);
        }
        __syncthreads();

#pragma unroll
        for (int ks = 0; ks < 4; ks++) {
            const int kb = ks * 8;
            uint32_t af[2][4];
#pragma unroll
            for (int mi = 0; mi < 2; mi++) {
                const int r = wm + mi * 16 + lr;
                const int c = kb + lc;
                af[mi][0] = As[r][c];
                af[mi][1] = As[r + 8][c];
                af[mi][2] = As[r][c + 4];
                af[mi][3] = As[r + 8][c + 4];
            }
            uint32_t bf[2][2];
#pragma unroll
            for (int ni = 0; ni < 2; ni++) {
                const int cc = wn + ni * 8 + lr;
                const int rr = kb + lc;
                bf[ni][0] = Bs[rr][cc];
                bf[ni][1] = Bs[rr + 4][cc];
            }
#pragma unroll
            for (int mi = 0; mi < 2; mi++)
#pragma unroll
                for (int ni = 0; ni < 2; ni++)
                    mma8(acc[mi][ni], af[mi], bf[ni]);
        }
        __syncthreads();
    }

#pragma unroll
    for (int mi = 0; mi < 2; mi++) {
#pragma unroll
        for (int ni = 0; ni < 2; ni++) {
            const int r0 = bm + wm + mi * 16 + lr;
            const int c0 = bn + wn + ni * 8 + lc * 2;
            float b1v0 = bias1 ? bias1[c0]     : 0.0f;
            float b1v1 = bias1 ? bias1[c0 + 1] : 0.0f;
#pragma unroll
            for (int h = 0; h < 2; h++) {
                float x0 = acc[mi][ni][h * 2 + 0] + b1v0;
                float x1 = acc[mi][ni][h * 2 + 1] + b1v1;
                if (EPI == 2) { x0 = fmaxf(x0, 0.0f); x1 = fmaxf(x1, 0.0f); }
                if (HOUT) {
                    *(uint32_t*)(Ch + (size_t)(r0 + h * 8) * N + c0) = packh(x0, x1);
                } else {
                    *(float2*)(C + (size_t)(r0 + h * 8) * N + c0) = make_float2(x0, x1);
                }
            }
        }
    }
}

// ---------------------------------------------------------------------------
// Attention reduction: score = E@vW + vb, softmax over S, context; builds xc.
// ---------------------------------------------------------------------------
__global__ __launch_bounds__(256) void attn_reduce(
    const float* __restrict__ attn, const float* __restrict__ vW,
    const float* __restrict__ vb,  const int* __restrict__ inputs,
    const float* __restrict__ emb, float* __restrict__ out_alpha)
{
    __shared__ float sc[SS];
    const int b = blockIdx.x;
    const int tid = threadIdx.x;
    const int warp = tid >> 5;
    const int lane = tid & 31;

#pragma unroll
    for (int q = 0; q < 8; q++) {
        const int s = warp * 8 + q;
        const float* e = g_E + (size_t)(b * SS + s) * UU;
        float acc = 0.0f;
        for (int u = lane; u < UU; u += 32) acc += e[u] * vW[u];
#pragma unroll
        for (int o = 16; o; o >>= 1) acc += __shfl_xor_sync(0xffffffffu, acc, o);
        if (lane == 0) sc[s] = acc + vb[0];
    }
    __syncthreads();

    if (warp == 0) {
        float v0 = sc[lane], v1 = sc[lane + 32];
        float m = fmaxf(v0, v1);
#pragma unroll
        for (int o = 16; o; o >>= 1) m = fmaxf(m, __shfl_xor_sync(0xffffffffu, m, o));
        float e0 = expf(v0 - m), e1 = expf(v1 - m);
        float ssum = e0 + e1;
#pragma unroll
        for (int o = 16; o; o >>= 1) ssum += __shfl_xor_sync(0xffffffffu, ssum, o);
        const float inv = 1.0f / ssum;
        sc[lane]      = e0 * inv;
        sc[lane + 32] = e1 * inv;
        out_alpha[b * SS + lane]      = e0 * inv;
        out_alpha[b * SS + lane + 32] = e1 * inv;
    }
    __syncthreads();

    const int erow = inputs[b];
    for (int u = tid; u < UU; u += 256) {
        float c = 0.0f;
        const float* ap = attn + (size_t)(b * SS) * UU + u;
#pragma unroll 8
        for (int s = 0; s < SS; s++) c += sc[s] * ap[(size_t)s * UU];
        g_xc[b * XCC + UU + u] = c;
        g_xc[b * XCC + u] = emb[(size_t)erow * UU + u];
    }
}

// ---------------------------------------------------------------------------
// GRU gates (h = 0): state = (1-z)*tanh(xh + r*b1h), z/r sigmoid.
// ---------------------------------------------------------------------------
__global__ __launch_bounds__(256) void gru_gates(
    const float* __restrict__ gru_b, float* __restrict__ out_state)
{
    const int i = blockIdx.x * blockDim.x + threadIdx.x;
    const int b = i >> 9;
    const int n = i & 511;
    const float* gb1 = gru_b + G3;
    const float* u = g_U + (size_t)b * G3;
    const float xz = u[n]        + gb1[n];
    const float xr = u[512 + n]  + gb1[512 + n];
    const float xh = u[1024 + n];
    const float z = 1.0f / (1.0f + expf(-xz));
    const float r = 1.0f / (1.0f + expf(-xr));
    const float hh = tanhf(xh + r * gb1[1024 + n]);
    out_state[i] = (1.0f - z) * hh;
}

// ---------------------------------------------------------------------------
extern "C" void kernel_launch(void* const* d_in, const int* in_sizes, int n_in,
                              void* d_out, int out_size)
{
    (void)in_sizes; (void)n_in; (void)out_size;

    const int*   inputs = (const int*)  d_in[0];
    const float* attn   = (const float*)d_in[1];
    const float* W0     = (const float*)d_in[2];
    const float* b0     = (const float*)d_in[3];
    // d_in[4] = W1 (unused: hidden0 == 0)
    const float* b1     = (const float*)d_in[5];
    const float* vW     = (const float*)d_in[6];
    const float* vb     = (const float*)d_in[7];
    const float* emb    = (const float*)d_in[8];
    const float* gru_k  = (const float*)d_in[9];
    // d_in[10] = gru_rk (unused: h == 0)
    const float* gru_b  = (const float*)d_in[11];
    const float* dW     = (const float*)d_in[12];
    const float* db     = (const float*)d_in[13];
    const float* oW     = (const float*)d_in[14];
    const float* ob     = (const float*)d_in[15];
    float* out = (float*)d_out;

    float *pE, *pXC, *pU;
    __half *pYH, *pAH, *pW0T, *pOWT;
    cudaGetSymbolAddress((void**)&pE,   g_E);
    cudaGetSymbolAddress((void**)&pXC,  g_xc);
    cudaGetSymbolAddress((void**)&pU,   g_U);
    cudaGetSymbolAddress((void**)&pYH,  g_yh);
    cudaGetSymbolAddress((void**)&pAH,  g_attn_h);
    cudaGetSymbolAddress((void**)&pW0T, g_W0t);
    cudaGetSymbolAddress((void**)&pOWT, g_oWt);

    // --- Pre-pass: fp16 conversions / transposes (pure streaming) ---
    cvt_h<<<(BB*SS*UU)/1024, 256>>>(attn, pAH);
    transpose_h<<<dim3(UU/32, UU/32), dim3(32, 8)>>>(W0, pW0T, UU, UU);
    transpose_h<<<dim3(VV/32, UU/32), dim3(32, 8)>>>(oW, pOWT, UU, VV);

    // 1) E = tanh(attn2d @ W0 + b0 + b1)   [8192 x 512 x 512]  fp16
    mma128h3<1><<<dim3(UU/128, (BB*SS)/128), 256>>>(
        pAH, pW0T, pE, b0, b1, BB*SS, UU, UU);

    // 2) score -> softmax -> alpha(out) -> context; build xc
    attn_reduce<<<BB, 256>>>(attn, vW, vb, inputs, emb, out + ALPHA_OFF);

    // 3) U = xc @ gru_k + gru_b[0]          [128 x 1536 x 1024] tf32
    mma64<0,0><<<dim3(G3/64, BB/64), 256>>>(pXC, gru_k, pU, nullptr, gru_b,
                                            BB, G3, XCC);
    // 4) gates -> state (straight into d_out)
    gru_gates<<<(BB*UU)/256, 256>>>(gru_b, out + STATE_OFF);

    // 5) y = relu(state @ dW + db)          [128 x 512 x 512] tf32, fp16 out
    mma64<2,1><<<dim3(UU/64, BB/64), 256>>>(out + STATE_OFF, dW, nullptr, pYH,
                                            db, BB, UU, UU);
    // 6) logits = y @ oW + ob               [128 x 32000 x 512] fp16
    mma128h3<0><<<dim3(VV/128, 1), 256>>>(
        pYH, pOWT, out, ob, nullptr, BB, VV, UU);
}

// round 12
// speedup vs baseline: 1.0277x; 1.0277x over previous
#include <cuda_runtime.h>
#include <cuda_fp16.h>
#include <math.h>
#include <stdint.h>

// Problem dims
#define BB 128
#define SS 64
#define UU 512
#define VV 32000
#define XCC 1024   // 2U
#define G3 1536    // 3U

// Output layout: [logits (128*32000)] [state (128*512)] [alpha (128*64)]
#define STATE_OFF (BB*VV)
#define ALPHA_OFF (BB*VV + BB*UU)

// Scratch (device globals: allocation-free). 16B-aligned for vector access.
__device__ __align__(16) float  g_E[BB*SS*UU];       // tanh(attn@W0+b0+b1)
__device__ __align__(16) float  g_xc[BB*XCC];        // [emb gather | context]
__device__ __align__(16) float  g_U[BB*G3];          // xc@gru_k + gru_b[0]
__device__ __align__(16) __half g_yh[BB*UU];         // relu(state@dW+db), fp16
__device__ __align__(16) __half g_attn_h[BB*SS*UU];  // attn in fp16
__device__ __align__(16) __half g_W0t[UU*UU];        // W0^T fp16 [N][K]
__device__ __align__(16) __half g_oWt[(size_t)VV*UU];// oW^T fp16 [N][K]

__device__ __forceinline__ uint32_t f2tf32(float x) {
    uint32_t r; asm("cvt.rna.tf32.f32 %0, %1;" : "=r"(r) : "f"(x)); return r;
}

__device__ __forceinline__ uint32_t packh(float a, float b) {
    __half2 v;
    v.x = __float2half_rn(a);
    v.y = __float2half_rn(b);
    return *(uint32_t*)&v;
}

__device__ __forceinline__ void mma8(float* c, const uint32_t* a, const uint32_t* b) {
    asm volatile(
        "mma.sync.aligned.m16n8k8.row.col.f32.tf32.tf32.f32 "
        "{%0,%1,%2,%3},{%4,%5,%6,%7},{%8,%9},{%0,%1,%2,%3};"
        : "+f"(c[0]), "+f"(c[1]), "+f"(c[2]), "+f"(c[3])
        : "r"(a[0]), "r"(a[1]), "r"(a[2]), "r"(a[3]),
          "r"(b[0]), "r"(b[1]));
}

__device__ __forceinline__ void mma16h(float* c, const uint32_t* a, const uint32_t* b) {
    asm volatile(
        "mma.sync.aligned.m16n8k16.row.col.f32.f16.f16.f32 "
        "{%0,%1,%2,%3},{%4,%5,%6,%7},{%8,%9},{%0,%1,%2,%3};"
        : "+f"(c[0]), "+f"(c[1]), "+f"(c[2]), "+f"(c[3])
        : "r"(a[0]), "r"(a[1]), "r"(a[2]), "r"(a[3]),
          "r"(b[0]), "r"(b[1]));
}

// ---------------------------------------------------------------------------
// Pre-pass: f32 -> fp16 elementwise (same layout). n % 1024 == 0.
// ---------------------------------------------------------------------------
__global__ __launch_bounds__(256) void cvt_h(
    const float* __restrict__ src, __half* __restrict__ dst)
{
    const int i = (blockIdx.x * 256 + threadIdx.x) * 4;
    float4 v = *(const float4*)(src + i);
    *(uint2*)(dst + i) = make_uint2(packh(v.x, v.y), packh(v.z, v.w));
}

// ---------------------------------------------------------------------------
// Pre-pass: transpose + cvt: src f32 [K][N] -> dst fp16 [N][K]. 32x32 tiles.
// blockDim (32, 8). grid (N/32, K/32).
// ---------------------------------------------------------------------------
__global__ __launch_bounds__(256) void transpose_h(
    const float* __restrict__ src, __half* __restrict__ dst, int K, int N)
{
    __shared__ float t[32][33];
    const int n0 = blockIdx.x * 32;
    const int k0 = blockIdx.y * 32;
    const int tx = threadIdx.x;
#pragma unroll
    for (int j = threadIdx.y; j < 32; j += 8)
        t[j][tx] = src[(size_t)(k0 + j) * N + n0 + tx];
    __syncthreads();
#pragma unroll
    for (int j = threadIdx.y; j < 32; j += 8)
        dst[(size_t)(n0 + j) * K + k0 + tx] = __float2half_rn(t[tx][j]);
}

// ---------------------------------------------------------------------------
// FP16 mma.sync GEMM, DOUBLE-BUFFERED. Block 128x128, BK=32, 256 threads
// (8 warps 2x4), warp tile 64x32. Inputs pre-converted fp16:
//   A [M][K] row-major, Bt [N][K] row-major (B transposed).
// Static smem: 2 buffers x (A 10240 + B 10240) = 40960 B. 80-byte row pitch:
// fragment LDS conflict-free. Register prefetch of chunk c+1 overlaps the
// compute of chunk c; one __syncthreads per chunk.
// C = epi(...) f32. EPI: 0 bias, 1 bias1+bias2 tanh. K%32==0.
// ---------------------------------------------------------------------------
template<int EPI>
__global__ __launch_bounds__(256, 2) void mma128h3(
    const __half* __restrict__ A, const __half* __restrict__ Bt,
    float* __restrict__ C,
    const float* __restrict__ bias1, const float* __restrict__ bias2,
    int M, int N, int K)
{
    __shared__ __align__(16) char sm[2][20480];   // per buffer: A @0, B @10240

    const int tid  = threadIdx.x;
    const int warp = tid >> 5;
    const int lane = tid & 31;
    const int bm   = blockIdx.y * 128;
    const int bn   = blockIdx.x * 128;
    const int wm   = (warp >> 2) * 64;
    const int wn   = (warp & 3) * 32;
    const int lr   = lane >> 2;
    const int lc   = lane & 3;

    // Fill: thread t handles row (t>>1), 32-byte segment (t&1) of both tiles.
    const int f_row = tid >> 1;
    const int f_sh  = (tid & 1) * 16;   // half offset within row (0 or 16)
    const __half* pa = A  + (size_t)(bm + f_row) * K + f_sh;
    const __half* pb = Bt + (size_t)(bn + f_row) * K + f_sh;
    const int dOff = f_row * 80 + f_sh * 2;   // byte offset within a tile

    float acc[4][4][4];
#pragma unroll
    for (int mi = 0; mi < 4; mi++)
#pragma unroll
        for (int ni = 0; ni < 4; ni++)
#pragma unroll
            for (int q = 0; q < 4; q++) acc[mi][ni][q] = 0.0f;

    const int NC = K >> 5;

    // Preload + store chunk 0 into buffer 0
    uint4 ra0 = *(const uint4*)(pa);
    uint4 ra1 = *(const uint4*)(pa + 8);
    uint4 rb0 = *(const uint4*)(pb);
    uint4 rb1 = *(const uint4*)(pb + 8);
    *(uint4*)(sm[0] + dOff)          = ra0;
    *(uint4*)(sm[0] + dOff + 16)     = ra1;
    *(uint4*)(sm[0] + 10240 + dOff)      = rb0;
    *(uint4*)(sm[0] + 10240 + dOff + 16) = rb1;
    __syncthreads();

    for (int c = 0; c < NC; ++c) {
        const int cur  = c & 1;
        const bool more = (c + 1) < NC;

        // Prefetch next chunk into registers (overlaps compute below)
        if (more) {
            const int k0 = (c + 1) << 5;
            ra0 = *(const uint4*)(pa + k0);
            ra1 = *(const uint4*)(pa + k0 + 8);
            rb0 = *(const uint4*)(pb + k0);
            rb1 = *(const uint4*)(pb + k0 + 8);
        }

        // Compute current buffer: 2 k16 slices
        const char* smA = sm[cur];
        const char* smB = sm[cur] + 10240;
#pragma unroll
        for (int ks = 0; ks < 2; ks++) {
            const int kq = ks * 8;
            uint32_t af[4][4];
#pragma unroll
            for (int mi = 0; mi < 4; mi++) {
                const int r = wm + mi * 16 + lr;
                af[mi][0] = *(const uint32_t*)(smA + r * 80 + (kq + lc) * 4);
                af[mi][1] = *(const uint32_t*)(smA + (r + 8) * 80 + (kq + lc) * 4);
                af[mi][2] = *(const uint32_t*)(smA + r * 80 + (kq + 4 + lc) * 4);
                af[mi][3] = *(const uint32_t*)(smA + (r + 8) * 80 + (kq + 4 + lc) * 4);
            }
            uint32_t bf[4][2];
#pragma unroll
            for (int ni = 0; ni < 4; ni++) {
                const int cc = wn + ni * 8 + lr;
                bf[ni][0] = *(const uint32_t*)(smB + cc * 80 + (kq + lc) * 4);
                bf[ni][1] = *(const uint32_t*)(smB + cc * 80 + (kq + 4 + lc) * 4);
            }
#pragma unroll
            for (int mi = 0; mi < 4; mi++)
#pragma unroll
                for (int ni = 0; ni < 4; ni++)
                    mma16h(acc[mi][ni], af[mi], bf[ni]);
        }

        // Store prefetched chunk into the other buffer (last read before the
        // PREVIOUS sync -> race-free), then one barrier.
        if (more) {
            char* nb = sm[cur ^ 1];
            *(uint4*)(nb + dOff)          = ra0;
            *(uint4*)(nb + dOff + 16)     = ra1;
            *(uint4*)(nb + 10240 + dOff)      = rb0;
            *(uint4*)(nb + 10240 + dOff + 16) = rb1;
        }
        __syncthreads();
    }

    // Epilogue
#pragma unroll
    for (int mi = 0; mi < 4; mi++) {
#pragma unroll
        for (int ni = 0; ni < 4; ni++) {
            const int r0 = bm + wm + mi * 16 + lr;
            const int c0 = bn + wn + ni * 8 + lc * 2;
            float b1v0 = bias1 ? bias1[c0]     : 0.0f;
            float b1v1 = bias1 ? bias1[c0 + 1] : 0.0f;
#pragma unroll
            for (int h = 0; h < 2; h++) {
                float x0 = acc[mi][ni][h * 2 + 0] + b1v0;
                float x1 = acc[mi][ni][h * 2 + 1] + b1v1;
                if (EPI == 1) {
                    x0 = tanhf(x0 + bias2[c0]);
                    x1 = tanhf(x1 + bias2[c0 + 1]);
                }
                *(float2*)(C + (size_t)(r0 + h * 8) * N + c0) = make_float2(x0, x1);
            }
        }
    }
}

// ---------------------------------------------------------------------------
// TF32 MMA GEMM, 64x64 block tile, BK=32, 256 threads, warp tile 32x16.
// HOUT=1: write fp16 to Ch instead of f32 to C.
// ---------------------------------------------------------------------------
template<int EPI, int HOUT>
__global__ __launch_bounds__(256) void mma64(
    const float* __restrict__ A, const float* __restrict__ Bm,
    float* __restrict__ C, __half* __restrict__ Ch,
    const float* __restrict__ bias1,
    int M, int N, int K)
{
    __shared__ uint32_t As[64][36];
    __shared__ uint32_t Bs[32][72];

    const int tid  = threadIdx.x;
    const int warp = tid >> 5;
    const int lane = tid & 31;
    const int wm   = (warp >> 2) * 32;
    const int wn   = (warp & 3) * 16;
    const int bm   = blockIdx.y * 64;
    const int bn   = blockIdx.x * 64;
    const int lr   = lane >> 2;
    const int lc   = lane & 3;

    float acc[2][2][4];
#pragma unroll
    for (int mi = 0; mi < 2; mi++)
#pragma unroll
        for (int ni = 0; ni < 2; ni++)
#pragma unroll
            for (int q = 0; q < 4; q++) acc[mi][ni][q] = 0.0f;

    for (int k0 = 0; k0 < K; k0 += 32) {
#pragma unroll
        for (int it = 0; it < 2; it++) {
            const int idx = it * 256 + tid;
            const int r  = idx >> 3;
            const int kq = (idx & 7) * 4;
            float4 v = *(const float4*)(A + (size_t)(bm + r) * K + k0 + kq);
            As[r][kq + 0] = f2tf32(v.x);
            As[r][kq + 1] = f2tf32(v.y);
            As[r][kq + 2] = f2tf32(v.z);
            As[r][kq + 3] = f2tf32(v.w);
        }
#pragma unroll
        for (int it = 0; it < 2; it++) {
            const int idx = it * 256 + tid;
            const int r  = idx >> 4;
            const int cq = (idx & 15) * 4;
            float4 v = *(const float4*)(Bm + (size_t)(k0 + r) * N + bn + cq);
            Bs[r][cq + 0] = f2tf32(v.x);
            Bs[r][cq + 1] = f2tf32(v.y);
            Bs[r][cq + 2] = f2tf32(v.z);
            Bs[r][cq + 3] = f2tf32(v.w);
        }
        __syncthreads();

#pragma unroll
        for (int ks = 0; ks < 4; ks++) {
            const int kb = ks * 8;
            uint32_t af[2][4];
#pragma unroll
            for (int mi = 0; mi < 2; mi++) {
                const int r = wm + mi * 16 + lr;
                const int c = kb + lc;
                af[mi][0] = As[r][c];
                af[mi][1] = As[r + 8][c];
                af[mi][2] = As[r][c + 4];
                af[mi][3] = As[r + 8][c + 4];
            }
            uint32_t bf[2][2];
#pragma unroll
            for (int ni = 0; ni < 2; ni++) {
                const int cc = wn + ni * 8 + lr;
                const int rr = kb + lc;
                bf[ni][0] = Bs[rr][cc];
                bf[ni][1] = Bs[rr + 4][cc];
            }
#pragma unroll
            for (int mi = 0; mi < 2; mi++)
#pragma unroll
                for (int ni = 0; ni < 2; ni++)
                    mma8(acc[mi][ni], af[mi], bf[ni]);
        }
        __syncthreads();
    }

#pragma unroll
    for (int mi = 0; mi < 2; mi++) {
#pragma unroll
        for (int ni = 0; ni < 2; ni++) {
            const int r0 = bm + wm + mi * 16 + lr;
            const int c0 = bn + wn + ni * 8 + lc * 2;
            float b1v0 = bias1 ? bias1[c0]     : 0.0f;
            float b1v1 = bias1 ? bias1[c0 + 1] : 0.0f;
#pragma unroll
            for (int h = 0; h < 2; h++) {
                float x0 = acc[mi][ni][h * 2 + 0] + b1v0;
                float x1 = acc[mi][ni][h * 2 + 1] + b1v1;
                if (EPI == 2) { x0 = fmaxf(x0, 0.0f); x1 = fmaxf(x1, 0.0f); }
                if (HOUT) {
                    *(uint32_t*)(Ch + (size_t)(r0 + h * 8) * N + c0) = packh(x0, x1);
                } else {
                    *(float2*)(C + (size_t)(r0 + h * 8) * N + c0) = make_float2(x0, x1);
                }
            }
        }
    }
}

// ---------------------------------------------------------------------------
// Attention reduction: score = E@vW + vb, softmax over S, context; builds xc.
// ---------------------------------------------------------------------------
__global__ __launch_bounds__(256) void attn_reduce(
    const float* __restrict__ attn, const float* __restrict__ vW,
    const float* __restrict__ vb,  const int* __restrict__ inputs,
    const float* __restrict__ emb, float* __restrict__ out_alpha)
{
    __shared__ float sc[SS];
    const int b = blockIdx.x;
    const int tid = threadIdx.x;
    const int warp = tid >> 5;
    const int lane = tid & 31;

#pragma unroll
    for (int q = 0; q < 8; q++) {
        const int s = warp * 8 + q;
        const float* e = g_E + (size_t)(b * SS + s) * UU;
        float acc = 0.0f;
        for (int u = lane; u < UU; u += 32) acc += e[u] * vW[u];
#pragma unroll
        for (int o = 16; o; o >>= 1) acc += __shfl_xor_sync(0xffffffffu, acc, o);
        if (lane == 0) sc[s] = acc + vb[0];
    }
    __syncthreads();

    if (warp == 0) {
        float v0 = sc[lane], v1 = sc[lane + 32];
        float m = fmaxf(v0, v1);
#pragma unroll
        for (int o = 16; o; o >>= 1) m = fmaxf(m, __shfl_xor_sync(0xffffffffu, m, o));
        float e0 = expf(v0 - m), e1 = expf(v1 - m);
        float ssum = e0 + e1;
#pragma unroll
        for (int o = 16; o; o >>= 1) ssum += __shfl_xor_sync(0xffffffffu, ssum, o);
        const float inv = 1.0f / ssum;
        sc[lane]      = e0 * inv;
        sc[lane + 32] = e1 * inv;
        out_alpha[b * SS + lane]      = e0 * inv;
        out_alpha[b * SS + lane + 32] = e1 * inv;
    }
    __syncthreads();

    const int erow = inputs[b];
    for (int u = tid; u < UU; u += 256) {
        float c = 0.0f;
        const float* ap = attn + (size_t)(b * SS) * UU + u;
#pragma unroll 8
        for (int s = 0; s < SS; s++) c += sc[s] * ap[(size_t)s * UU];
        g_xc[b * XCC + UU + u] = c;
        g_xc[b * XCC + u] = emb[(size_t)erow * UU + u];
    }
}

// ---------------------------------------------------------------------------
// GRU gates (h = 0): state = (1-z)*tanh(xh + r*b1h), z/r sigmoid.
// ---------------------------------------------------------------------------
__global__ __launch_bounds__(256) void gru_gates(
    const float* __restrict__ gru_b, float* __restrict__ out_state)
{
    const int i = blockIdx.x * blockDim.x + threadIdx.x;
    const int b = i >> 9;
    const int n = i & 511;
    const float* gb1 = gru_b + G3;
    const float* u = g_U + (size_t)b * G3;
    const float xz = u[n]        + gb1[n];
    const float xr = u[512 + n]  + gb1[512 + n];
    const float xh = u[1024 + n];
    const float z = 1.0f / (1.0f + expf(-xz));
    const float r = 1.0f / (1.0f + expf(-xr));
    const float hh = tanhf(xh + r * gb1[1024 + n]);
    out_state[i] = (1.0f - z) * hh;
}

// ---------------------------------------------------------------------------
extern "C" void kernel_launch(void* const* d_in, const int* in_sizes, int n_in,
                              void* d_out, int out_size)
{
    (void)in_sizes; (void)n_in; (void)out_size;

    const int*   inputs = (const int*)  d_in[0];
    const float* attn   = (const float*)d_in[1];
    const float* W0     = (const float*)d_in[2];
    const float* b0     = (const float*)d_in[3];
    // d_in[4] = W1 (unused: hidden0 == 0)
    const float* b1     = (const float*)d_in[5];
    const float* vW     = (const float*)d_in[6];
    const float* vb     = (const float*)d_in[7];
    const float* emb    = (const float*)d_in[8];
    const float* gru_k  = (const float*)d_in[9];
    // d_in[10] = gru_rk (unused: h == 0)
    const float* gru_b  = (const float*)d_in[11];
    const float* dW     = (const float*)d_in[12];
    const float* db     = (const float*)d_in[13];
    const float* oW     = (const float*)d_in[14];
    const float* ob     = (const float*)d_in[15];
    float* out = (float*)d_out;

    float *pE, *pXC, *pU;
    __half *pYH, *pAH, *pW0T, *pOWT;
    cudaGetSymbolAddress((void**)&pE,   g_E);
    cudaGetSymbolAddress((void**)&pXC,  g_xc);
    cudaGetSymbolAddress((void**)&pU,   g_U);
    cudaGetSymbolAddress((void**)&pYH,  g_yh);
    cudaGetSymbolAddress((void**)&pAH,  g_attn_h);
    cudaGetSymbolAddress((void**)&pW0T, g_W0t);
    cudaGetSymbolAddress((void**)&pOWT, g_oWt);

    // --- Pre-pass: fp16 conversions / transposes (pure streaming) ---
    cvt_h<<<(BB*SS*UU)/1024, 256>>>(attn, pAH);
    transpose_h<<<dim3(UU/32, UU/32), dim3(32, 8)>>>(W0, pW0T, UU, UU);
    transpose_h<<<dim3(VV/32, UU/32), dim3(32, 8)>>>(oW, pOWT, UU, VV);

    // 1) E = tanh(attn2d @ W0 + b0 + b1)   [8192 x 512 x 512]  fp16 dbl-buf
    mma128h3<1><<<dim3(UU/128, (BB*SS)/128), 256>>>(
        pAH, pW0T, pE, b0, b1, BB*SS, UU, UU);

    // 2) score -> softmax -> alpha(out) -> context; build xc
    attn_reduce<<<BB, 256>>>(attn, vW, vb, inputs, emb, out + ALPHA_OFF);

    // 3) U = xc @ gru_k + gru_b[0]          [128 x 1536 x 1024] tf32
    mma64<0,0><<<dim3(G3/64, BB/64), 256>>>(pXC, gru_k, pU, nullptr, gru_b,
                                            BB, G3, XCC);
    // 4) gates -> state (straight into d_out)
    gru_gates<<<(BB*UU)/256, 256>>>(gru_b, out + STATE_OFF);

    // 5) y = relu(state @ dW + db)          [128 x 512 x 512] tf32, fp16 out
    mma64<2,1><<<dim3(UU/64, BB/64), 256>>>(out + STATE_OFF, dW, nullptr, pYH,
                                            db, BB, UU, UU);
    // 6) logits = y @ oW + ob               [128 x 32000 x 512] fp16 dbl-buf
    mma128h3<0><<<dim3(VV/128, 1), 256>>>(
        pYH, pOWT, out, ob, nullptr, BB, VV, UU);
}